// round 16
// baseline (speedup 1.0000x reference)
#include <cuda_runtime.h>
#include <cuda_bf16.h>
#include <math.h>
#include <stdint.h>

// ---------------- problem constants ----------------
#define NB   8
#define NN   4096
#define CVD  256
#define CTD  512
#define NT   77
#define TPAD 96
#define NHH  8
#define DH   32
#define TOPM 5
#define ROWS (NB*NN)
#define FFN  (4*CVD)

// ---------------- scratch ----------------
__device__ float g_x[ROWS*CVD];
__device__ float g_q[ROWS*CVD];
__device__ float g_kT[NB*NHH*DH*TPAD];
__device__ float g_v[NB*NT*CVD];
__device__ int   g_pad[NB*NT];
__device__ float g_aligned[ROWS*CVD];
__device__ float g_proj[ROWS*CVD];
__device__ float g_y2[ROWS*CVD];
__device__ uint2 g_hdnP[ROWS*FFN/2];     // FFN hidden, packed {hi_pair, lo_pair}
// pre-split weights, k-pair-packed bf16x2 hi/lo, layout [K/2][N] (coalesced)
__device__ uint32_t g_wqh[(CVD/2)*CVD], g_wql[(CVD/2)*CVD];
__device__ uint32_t g_woh[(CVD/2)*CVD], g_wol[(CVD/2)*CVD];
__device__ uint32_t g_w1h[(CVD/2)*FFN], g_w1l[(CVD/2)*FFN];
__device__ uint32_t g_w2h[(FFN/2)*CVD], g_w2l[(FFN/2)*CVD];

__device__ __forceinline__ void bf16_split_pack(float x0, float x1, uint32_t& hi, uint32_t& lo) {
    __nv_bfloat16 h0 = __float2bfloat16_rn(x0);
    __nv_bfloat16 h1 = __float2bfloat16_rn(x1);
    __nv_bfloat16 l0 = __float2bfloat16_rn(x0 - __bfloat162float(h0));
    __nv_bfloat16 l1 = __float2bfloat16_rn(x1 - __bfloat162float(h1));
    hi = (uint32_t)__bfloat16_as_ushort(h0) | ((uint32_t)__bfloat16_as_ushort(h1) << 16);
    lo = (uint32_t)__bfloat16_as_ushort(l0) | ((uint32_t)__bfloat16_as_ushort(l1) << 16);
}

// ---------------- weight split+pack: W[K][N] fp32 -> Wh/Wl[K/2][N] bf16x2 ----------------
__global__ __launch_bounds__(256) void wsplit_kernel(const float* __restrict__ W,
                                                     uint32_t* __restrict__ Wh,
                                                     uint32_t* __restrict__ Wl,
                                                     int N) {
    int idx = blockIdx.x * 256 + threadIdx.x;
    int k2 = idx / N, n = idx - k2 * N;
    float x0 = W[(size_t)(2*k2) * N + n];
    float x1 = W[(size_t)(2*k2 + 1) * N + n];
    uint32_t h, l;
    bf16_split_pack(x0, x1, h, l);
    Wh[idx] = h; Wl[idx] = l;
}

// ---------------- LN1 ----------------
__global__ __launch_bounds__(256) void ln1_kernel(const float* __restrict__ in,
                                                  const float* __restrict__ g,
                                                  const float* __restrict__ b) {
    int warp = (blockIdx.x * blockDim.x + threadIdx.x) >> 5;
    int lane = threadIdx.x & 31;
    const float* row = in + (size_t)warp * CVD;
    float v[8]; float s = 0.f, ss = 0.f;
#pragma unroll
    for (int i = 0; i < 8; i++) { v[i] = row[lane*8 + i]; s += v[i]; ss += v[i]*v[i]; }
#pragma unroll
    for (int o = 16; o; o >>= 1) { s += __shfl_xor_sync(~0u, s, o); ss += __shfl_xor_sync(~0u, ss, o); }
    float mu  = s * (1.f/CVD);
    float inv = rsqrtf(ss * (1.f/CVD) - mu*mu + 1e-5f);
    float* orow = g_x + (size_t)warp * CVD;
#pragma unroll
    for (int i = 0; i < 8; i++) { int c = lane*8 + i; orow[c] = (v[i]-mu)*inv*g[c] + b[c]; }
}

// ---------------- LN2 + residual ----------------
__global__ __launch_bounds__(256) void ln2res_kernel(const float* __restrict__ g,
                                                     const float* __restrict__ b,
                                                     const float* __restrict__ alpha_p) {
    int warp = (blockIdx.x * blockDim.x + threadIdx.x) >> 5;
    int lane = threadIdx.x & 31;
    float alpha = alpha_p[0];
    const float* xr = g_x    + (size_t)warp * CVD;
    const float* pr = g_proj + (size_t)warp * CVD;
    float v[8]; float s = 0.f, ss = 0.f;
#pragma unroll
    for (int i = 0; i < 8; i++) {
        int c = lane*8 + i;
        v[i] = xr[c] + alpha * pr[c];
        s += v[i]; ss += v[i]*v[i];
    }
#pragma unroll
    for (int o = 16; o; o >>= 1) { s += __shfl_xor_sync(~0u, s, o); ss += __shfl_xor_sync(~0u, ss, o); }
    float mu  = s * (1.f/CVD);
    float inv = rsqrtf(ss * (1.f/CVD) - mu*mu + 1e-5f);
    float* orow = g_y2 + (size_t)warp * CVD;
#pragma unroll
    for (int i = 0; i < 8; i++) { int c = lane*8 + i; orow[c] = (v[i]-mu)*inv*g[c] + b[c]; }
}

// ---------------- K/V projection (per-token, proven best) ----------------
__global__ __launch_bounds__(256) void kv_kernel(const float* __restrict__ text,
                                                 const float* __restrict__ Wk, const float* __restrict__ bk,
                                                 const float* __restrict__ Wv, const float* __restrict__ bv) {
    int bt = blockIdx.x;
    int b  = bt / NT, t = bt - b * NT;
    int c  = threadIdx.x;
    __shared__ float txt[CTD];
    __shared__ float red[256];
    const float* trow = text + (size_t)bt * CTD;
    txt[c] = trow[c]; txt[c+256] = trow[c+256];
    __syncthreads();
    red[c] = fabsf(txt[c]) + fabsf(txt[c+256]);
    __syncthreads();
    for (int s = 128; s; s >>= 1) { if (c < s) red[c] += red[c+s]; __syncthreads(); }
    if (c == 0) g_pad[bt] = (red[0] <= 1e-6f);
    float kc = bk[c], vc = bv[c];
#pragma unroll 4
    for (int kk = 0; kk < CTD; kk++) {
        float tv = txt[kk];
        kc += tv * Wk[kk*CVD + c];
        vc += tv * Wv[kk*CVD + c];
    }
    float ss = kc * kc;
#pragma unroll
    for (int o = 16; o; o >>= 1) ss += __shfl_xor_sync(~0u, ss, o);
    kc /= fmaxf(sqrtf(ss), 1e-6f);
    int h = c >> 5, d = c & 31;
    g_kT[((b*NHH + h)*DH + d)*TPAD + t] = kc;
    g_v[(size_t)bt*CVD + c] = vc;
}

// ---------------- order-preserving float<->uint ----------------
__device__ __forceinline__ uint32_t ford(float f) {
    uint32_t u = __float_as_uint(f);
    return (u & 0x80000000u) ? ~u : (u | 0x80000000u);
}
__device__ __forceinline__ float finv(uint32_t m) {
    uint32_t u = (m & 0x80000000u) ? (m ^ 0x80000000u) : ~m;
    return __uint_as_float(u);
}

// ---------------- attention: 2 rows per block, warp per head; redux top-5 ----------------
__global__ __launch_bounds__(256) void attn_kernel(const float* __restrict__ logit_scale) {
    int row0 = blockIdx.x * 2;
    int b    = row0 >> 12;
    int tid  = threadIdx.x;
    int h = tid >> 5, lane = tid & 31;
    __shared__ float qs[2][CVD];
    __shared__ int   spad[NT];
    qs[0][tid] = g_q[(size_t)row0 * CVD + tid];
    qs[1][tid] = g_q[(size_t)(row0 + 1) * CVD + tid];
    if (tid < NT) spad[tid] = g_pad[b*NT + tid];
    __syncthreads();

    float ls = logit_scale[0];
    float scale = expf(fminf(fmaxf(ls, -2.f), 2.f)) * 0.17677669529663687f;

    const float* kT = g_kT + ((size_t)(b*NHH + h) * DH) * TPAD;
    float acc[2][3] = {};
#pragma unroll
    for (int d = 0; d < DH; d++) {
        const float* kr = kT + d*TPAD;
        float k0 = kr[lane], k1 = kr[lane + 32], k2 = kr[lane + 64];
        float q0 = qs[0][h*DH + d];
        float q1 = qs[1][h*DH + d];
        acc[0][0] += q0 * k0; acc[0][1] += q0 * k1; acc[0][2] += q0 * k2;
        acc[1][0] += q1 * k0; acc[1][1] += q1 * k1; acc[1][2] += q1 * k2;
    }

    bool p0 = spad[lane];
    bool p1 = (lane + 32 >= NT) || spad[lane + 32];
    bool p2 = (lane + 64 >= NT) || spad[lane + 64];

#pragma unroll
    for (int rr = 0; rr < 2; rr++) {
        float s0 = !p0 ? acc[rr][0] * scale : -INFINITY;
        float s1 = !p1 ? acc[rr][1] * scale : -INFINITY;
        float s2 = !p2 ? acc[rr][2] * scale : -INFINITY;

        uint32_t o0 = ford(s0), o1 = ford(s1), o2 = ford(s2);

        float topv[TOPM]; int topt[TOPM];
#pragma unroll
        for (int it = 0; it < TOPM; it++) {
            uint32_t loc = o0 > o1 ? o0 : o1;
            if (o2 > loc) loc = o2;
            uint32_t m = __reduce_max_sync(0xffffffffu, loc);
            topv[it] = finv(m);
            int t;
            unsigned b0 = __ballot_sync(0xffffffffu, o0 == m);
            if (b0) t = __ffs(b0) - 1;
            else {
                unsigned b1 = __ballot_sync(0xffffffffu, o1 == m);
                if (b1) t = 32 + __ffs(b1) - 1;
                else {
                    unsigned b2 = __ballot_sync(0xffffffffu, o2 == m);
                    t = 64 + __ffs(b2) - 1;
                }
            }
            topt[it] = t;
            if ((t & 31) == lane) {
                if (t < 32) o0 = 0u; else if (t < 64) o1 = 0u; else o2 = 0u;
            }
        }

        float outv = 0.f;
        float mx = topv[0];
        if (!(mx == -INFINITY)) {
            float e[TOPM]; float ws = 0.f;
#pragma unroll
            for (int i = 0; i < TOPM; i++) { e[i] = expf(topv[i] - mx); ws += e[i]; }
            float inv = 1.f / ws;
            const float* vb = g_v + (size_t)b * NT * CVD + h * DH + lane;
#pragma unroll
            for (int i = 0; i < TOPM; i++) outv += (e[i] * inv) * vb[(size_t)topt[i] * CVD];
        }
        g_aligned[(size_t)(row0 + rr) * CVD + h*DH + lane] = outv;
    }
}

// ---------------- mma / ldmatrix helpers ----------------
__device__ __forceinline__ void mma16(float* c, const uint32_t* a, const uint32_t* b) {
    asm volatile("mma.sync.aligned.m16n8k16.row.col.f32.bf16.bf16.f32 "
        "{%0,%1,%2,%3}, {%4,%5,%6,%7}, {%8,%9}, {%0,%1,%2,%3};"
        : "+f"(c[0]), "+f"(c[1]), "+f"(c[2]), "+f"(c[3])
        : "r"(a[0]), "r"(a[1]), "r"(a[2]), "r"(a[3]), "r"(b[0]), "r"(b[1]));
}
__device__ __forceinline__ void ldsm4(uint32_t* r, uint32_t saddr) {
    asm volatile("ldmatrix.sync.aligned.m8n8.x4.shared.b16 {%0,%1,%2,%3}, [%4];"
        : "=r"(r[0]), "=r"(r[1]), "=r"(r[2]), "=r"(r[3]) : "r"(saddr));
}

// ---------------- split-bf16 GEMM: A/B fragments via ldmatrix, pre-packed B weights ----------------
// APACK=0: A fp32 row-major [M][K], split at staging. APACK=1: A packed uint2{hi,lo} pairs [M][K/2].
// B: Bh/Bl packed bf16x2 [K/2][N]. mode: 0 plain, 1 gelu->packed outP, 2 l2norm, 3 +res.
#define ASTRIDE 12
#define BSTRIDE 12
template<int APACK>
__global__ __launch_bounds__(256) void gemm_bf16s_kernel(const void* __restrict__ Avoid,
                                                         const uint32_t* __restrict__ Bhp,
                                                         const uint32_t* __restrict__ Blp,
                                                         const float* __restrict__ bias,
                                                         const float* __restrict__ res,
                                                         float* __restrict__ outF,
                                                         uint2* __restrict__ outP,
                                                         int K, int N, int mode) {
    __shared__ uint32_t AhS[2][128*ASTRIDE], AlS[2][128*ASTRIDE];
    __shared__ uint32_t BhS[2][64*BSTRIDE], BlS[2][64*BSTRIDE];

    int tid  = threadIdx.x;
    int lane = tid & 31, wid = tid >> 5;
    int warpM = wid & 3, warpN = wid >> 2;
    int g = lane >> 2, t4 = lane & 3;
    int m0 = blockIdx.y * 128, n0 = blockIdx.x * 64;
    int mbase = warpM * 32, nbase = warpN * 32;

    float c[2][4][4];
#pragma unroll
    for (int i = 0; i < 2; i++)
#pragma unroll
        for (int j = 0; j < 4; j++)
#pragma unroll
            for (int l = 0; l < 4; l++) c[i][j][l] = 0.f;

    int ar   = tid >> 1;
    int ha   = tid & 1;
    int aoff = ar * ASTRIDE + ha * 4;
    int bn   = tid & 63;
    int k2b  = (tid >> 6) * 2;

    const float* ApF = (const float*)Avoid + (size_t)(m0 + ar) * K + 8*ha;        // APACK=0
    const uint2* ApP = (const uint2*)Avoid + (size_t)(m0 + ar) * (K/2) + 4*ha;    // APACK=1
    const uint32_t* Bph = Bhp + (size_t)k2b * N + n0 + bn;
    const uint32_t* Bpl = Blp + (size_t)k2b * N + n0 + bn;

    int lrow = lane & 15;
    int lkof = (lane >> 4) * 4;
    int bm   = lane >> 3;
    int brow = ((bm >> 1) << 3) + (lane & 7);
    int bkof = (bm & 1) * 4;

    float4 av0, av1;          // APACK=0 regs
    uint4  aq0, aq1;          // APACK=1 regs
    uint32_t bh0, bh1, bl0, bl1;

    if (APACK == 0) {
        av0 = *(const float4*)(ApF);
        av1 = *(const float4*)(ApF + 4);
    } else {
        aq0 = *(const uint4*)(ApP);
        aq1 = *(const uint4*)(ApP + 2);
    }
    bh0 = Bph[0]; bh1 = Bph[N];
    bl0 = Bpl[0]; bl1 = Bpl[N];

    // stage tile 0
    {
        if (APACK == 0) {
            uint32_t h0,l0,h1,l1,h2,l2,h3,l3;
            bf16_split_pack(av0.x, av0.y, h0, l0);
            bf16_split_pack(av0.z, av0.w, h1, l1);
            bf16_split_pack(av1.x, av1.y, h2, l2);
            bf16_split_pack(av1.z, av1.w, h3, l3);
            *(uint4*)&AhS[0][aoff] = make_uint4(h0, h1, h2, h3);
            *(uint4*)&AlS[0][aoff] = make_uint4(l0, l1, l2, l3);
        } else {
            *(uint4*)&AhS[0][aoff] = make_uint4(aq0.x, aq0.z, aq1.x, aq1.z);
            *(uint4*)&AlS[0][aoff] = make_uint4(aq0.y, aq0.w, aq1.y, aq1.w);
        }
        *(uint2*)&BhS[0][bn*BSTRIDE + k2b] = make_uint2(bh0, bh1);
        *(uint2*)&BlS[0][bn*BSTRIDE + k2b] = make_uint2(bl0, bl1);
    }

    int stage = 0;
    for (int k0 = 0; k0 < K; k0 += 16) {
        __syncthreads();
        bool more = (k0 + 16) < K;
        if (more) {
            if (APACK == 0) {
                av0 = *(const float4*)(ApF + k0 + 16);
                av1 = *(const float4*)(ApF + k0 + 20);
            } else {
                const uint2* ap = ApP + (k0 >> 1) + 8;
                aq0 = *(const uint4*)(ap);
                aq1 = *(const uint4*)(ap + 2);
            }
            const uint32_t* bph = Bph + (size_t)((k0 >> 1) + 8) * N;
            const uint32_t* bpl = Bpl + (size_t)((k0 >> 1) + 8) * N;
            bh0 = bph[0]; bh1 = bph[N];
            bl0 = bpl[0]; bl1 = bpl[N];
        }

        uint32_t ah[2][4], al[2][4], bh[4][2], blo[4][2];
#pragma unroll
        for (int mt = 0; mt < 2; mt++) {
            int r = mbase + mt*16 + lrow;
            uint32_t addrH = (uint32_t)__cvta_generic_to_shared(&AhS[stage][r*ASTRIDE + lkof]);
            uint32_t addrL = (uint32_t)__cvta_generic_to_shared(&AlS[stage][r*ASTRIDE + lkof]);
            ldsm4(ah[mt], addrH);
            ldsm4(al[mt], addrL);
        }
#pragma unroll
        for (int pair = 0; pair < 2; pair++) {
            int nrow = nbase + pair*16 + brow;
            uint32_t addrH = (uint32_t)__cvta_generic_to_shared(&BhS[stage][nrow*BSTRIDE + bkof]);
            uint32_t addrL = (uint32_t)__cvta_generic_to_shared(&BlS[stage][nrow*BSTRIDE + bkof]);
            uint32_t tH[4], tL[4];
            ldsm4(tH, addrH);
            ldsm4(tL, addrL);
            bh[pair*2  ][0] = tH[0]; bh[pair*2  ][1] = tH[1];
            bh[pair*2+1][0] = tH[2]; bh[pair*2+1][1] = tH[3];
            blo[pair*2  ][0] = tL[0]; blo[pair*2  ][1] = tL[1];
            blo[pair*2+1][0] = tL[2]; blo[pair*2+1][1] = tL[3];
        }
#pragma unroll
        for (int mt = 0; mt < 2; mt++)
#pragma unroll
            for (int nt = 0; nt < 4; nt++) {
                mma16(c[mt][nt], al[mt], bh[nt]);
                mma16(c[mt][nt], ah[mt], blo[nt]);
                mma16(c[mt][nt], ah[mt], bh[nt]);
            }

        if (more) {
            int ns = stage ^ 1;
            if (APACK == 0) {
                uint32_t h0,l0,h1,l1,h2,l2,h3,l3;
                bf16_split_pack(av0.x, av0.y, h0, l0);
                bf16_split_pack(av0.z, av0.w, h1, l1);
                bf16_split_pack(av1.x, av1.y, h2, l2);
                bf16_split_pack(av1.z, av1.w, h3, l3);
                *(uint4*)&AhS[ns][aoff] = make_uint4(h0, h1, h2, h3);
                *(uint4*)&AlS[ns][aoff] = make_uint4(l0, l1, l2, l3);
            } else {
                *(uint4*)&AhS[ns][aoff] = make_uint4(aq0.x, aq0.z, aq1.x, aq1.z);
                *(uint4*)&AlS[ns][aoff] = make_uint4(aq0.y, aq0.w, aq1.y, aq1.w);
            }
            *(uint2*)&BhS[ns][bn*BSTRIDE + k2b] = make_uint2(bh0, bh1);
            *(uint2*)&BlS[ns][bn*BSTRIDE + k2b] = make_uint2(bl0, bl1);
        }
        stage ^= 1;
    }

    // epilogue
#pragma unroll
    for (int mt = 0; mt < 2; mt++)
#pragma unroll
        for (int nt = 0; nt < 4; nt++) {
            int col = n0 + nbase + nt*8 + t4*2;
            float b0v = bias[col], b1v = bias[col + 1];
            c[mt][nt][0] += b0v; c[mt][nt][1] += b1v;
            c[mt][nt][2] += b0v; c[mt][nt][3] += b1v;
        }

    if (mode == 2) {
#pragma unroll
        for (int mt = 0; mt < 2; mt++) {
            float ss0 = 0.f, ss1 = 0.f;
#pragma unroll
            for (int nt = 0; nt < 4; nt++) {
                ss0 += c[mt][nt][0]*c[mt][nt][0] + c[mt][nt][1]*c[mt][nt][1];
                ss1 += c[mt][nt][2]*c[mt][nt][2] + c[mt][nt][3]*c[mt][nt][3];
            }
            ss0 += __shfl_xor_sync(~0u, ss0, 1); ss0 += __shfl_xor_sync(~0u, ss0, 2);
            ss1 += __shfl_xor_sync(~0u, ss1, 1); ss1 += __shfl_xor_sync(~0u, ss1, 2);
            float i0 = 1.f / fmaxf(sqrtf(ss0), 1e-6f);
            float i1 = 1.f / fmaxf(sqrtf(ss1), 1e-6f);
#pragma unroll
            for (int nt = 0; nt < 4; nt++) {
                c[mt][nt][0] *= i0; c[mt][nt][1] *= i0;
                c[mt][nt][2] *= i1; c[mt][nt][3] *= i1;
            }
        }
    }

#pragma unroll
    for (int mt = 0; mt < 2; mt++)
#pragma unroll
        for (int nt = 0; nt < 4; nt++) {
            int col = n0 + nbase + nt*8 + t4*2;
            size_t r0 = (size_t)(m0 + mbase + mt*16 + g);
            size_t r1 = r0 + 8;
            float v0 = c[mt][nt][0], v1 = c[mt][nt][1];
            float v2 = c[mt][nt][2], v3 = c[mt][nt][3];
            if (mode == 1) {
                v0 = 0.5f*v0*(1.f + erff(v0*0.70710678118654752f));
                v1 = 0.5f*v1*(1.f + erff(v1*0.70710678118654752f));
                v2 = 0.5f*v2*(1.f + erff(v2*0.70710678118654752f));
                v3 = 0.5f*v3*(1.f + erff(v3*0.70710678118654752f));
                uint32_t h, l;
                bf16_split_pack(v0, v1, h, l);
                outP[r0*(N/2) + (col >> 1)] = make_uint2(h, l);
                bf16_split_pack(v2, v3, h, l);
                outP[r1*(N/2) + (col >> 1)] = make_uint2(h, l);
            } else {
                if (mode == 3) {
                    v0 += res[r0*N + col]; v1 += res[r0*N + col + 1];
                    v2 += res[r1*N + col]; v3 += res[r1*N + col + 1];
                }
                *(float2*)&outF[r0*N + col] = make_float2(v0, v1);
                *(float2*)&outF[r1*N + col] = make_float2(v2, v3);
            }
        }
}

// ---------------- launch ----------------
extern "C" void kernel_launch(void* const* d_in, const int* in_sizes, int n_in,
                              void* d_out, int out_size) {
    const float* vis   = (const float*)d_in[0];
    const float* text  = (const float*)d_in[1];
    const float* Wq    = (const float*)d_in[2];
    const float* bq    = (const float*)d_in[3];
    const float* Wk    = (const float*)d_in[4];
    const float* bk    = (const float*)d_in[5];
    const float* Wv    = (const float*)d_in[6];
    const float* bv    = (const float*)d_in[7];
    const float* Wo    = (const float*)d_in[8];
    const float* bo    = (const float*)d_in[9];
    const float* g1    = (const float*)d_in[10];
    const float* b1    = (const float*)d_in[11];
    const float* g2    = (const float*)d_in[12];
    const float* b2    = (const float*)d_in[13];
    const float* Wf1   = (const float*)d_in[14];
    const float* bf1   = (const float*)d_in[15];
    const float* Wf2   = (const float*)d_in[16];
    const float* bf2   = (const float*)d_in[17];
    const float* ls    = (const float*)d_in[18];
    const float* alpha = (const float*)d_in[19];
    float* out = (float*)d_out;

    float *px, *pq, *paligned, *pproj, *py2;
    uint2 *phdnP;
    uint32_t *pwqh, *pwql, *pwoh, *pwol, *pw1h, *pw1l, *pw2h, *pw2l;
    cudaGetSymbolAddress((void**)&px,       g_x);
    cudaGetSymbolAddress((void**)&pq,       g_q);
    cudaGetSymbolAddress((void**)&paligned, g_aligned);
    cudaGetSymbolAddress((void**)&pproj,    g_proj);
    cudaGetSymbolAddress((void**)&py2,      g_y2);
    cudaGetSymbolAddress((void**)&phdnP,    g_hdnP);
    cudaGetSymbolAddress((void**)&pwqh, g_wqh); cudaGetSymbolAddress((void**)&pwql, g_wql);
    cudaGetSymbolAddress((void**)&pwoh, g_woh); cudaGetSymbolAddress((void**)&pwol, g_wol);
    cudaGetSymbolAddress((void**)&pw1h, g_w1h); cudaGetSymbolAddress((void**)&pw1l, g_w1l);
    cudaGetSymbolAddress((void**)&pw2h, g_w2h); cudaGetSymbolAddress((void**)&pw2l, g_w2l);

    // fork side stream: weight splits (Wo/Wf1/Wf2) + kv, overlapping ln1 + q-GEMM
    cudaStream_t s2;
    cudaEvent_t evA, evB;
    cudaStreamCreateWithFlags(&s2, cudaStreamNonBlocking);
    cudaEventCreateWithFlags(&evA, cudaEventDisableTiming);
    cudaEventCreateWithFlags(&evB, cudaEventDisableTiming);

    cudaEventRecord(evA, 0);
    cudaStreamWaitEvent(s2, evA, 0);
    wsplit_kernel<<<(CVD/2)*CVD/256, 256, 0, s2>>>(Wo,  pwoh, pwol, CVD);
    wsplit_kernel<<<(CVD/2)*FFN/256, 256, 0, s2>>>(Wf1, pw1h, pw1l, FFN);
    wsplit_kernel<<<(FFN/2)*CVD/256, 256, 0, s2>>>(Wf2, pw2h, pw2l, CVD);
    kv_kernel<<<NB*NT, 256, 0, s2>>>(text, Wk, bk, Wv, bv);
    cudaEventRecord(evB, s2);

    // main: Wq split -> ln1 -> q-GEMM
    wsplit_kernel<<<(CVD/2)*CVD/256, 256>>>(Wq, pwqh, pwql, CVD);
    ln1_kernel<<<ROWS/8, 256>>>(vis, g1, b1);
    gemm_bf16s_kernel<0><<<dim3(CVD/64, ROWS/128), 256>>>(
        px, pwqh, pwql, bq, nullptr, pq, nullptr, CVD, CVD, 2);

    cudaStreamWaitEvent(0, evB, 0);
    attn_kernel<<<ROWS/2, 256>>>(ls);
    gemm_bf16s_kernel<0><<<dim3(CVD/64, ROWS/128), 256>>>(
        paligned, pwoh, pwol, bo, nullptr, pproj, nullptr, CVD, CVD, 0);
    ln2res_kernel<<<ROWS/8, 256>>>(g2, b2, alpha);
    gemm_bf16s_kernel<0><<<dim3(FFN/64, ROWS/128), 256>>>(
        py2, pw1h, pw1l, bf1, nullptr, nullptr, phdnP, CVD, FFN, 1);
    gemm_bf16s_kernel<1><<<dim3(CVD/64, ROWS/128), 256>>>(
        phdnP, pw2h, pw2l, bf2, py2, out, nullptr, FFN, CVD, 3);
}

// round 17
// speedup vs baseline: 1.0046x; 1.0046x over previous
#include <cuda_runtime.h>
#include <cuda_bf16.h>
#include <math.h>
#include <stdint.h>

// ---------------- problem constants ----------------
#define NB   8
#define NN   4096
#define CVD  256
#define CTD  512
#define NT   77
#define TPAD 96
#define NHH  8
#define DH   32
#define TOPM 5
#define ROWS (NB*NN)
#define FFN  (4*CVD)

// ---------------- scratch ----------------
__device__ float g_x[ROWS*CVD];
__device__ float g_q[ROWS*CVD];
__device__ float g_kT[NB*NHH*DH*TPAD];
__device__ float g_v[NB*NT*CVD];
__device__ int   g_pad[NB*NT];
__device__ float g_aligned[ROWS*CVD];
__device__ float g_proj[ROWS*CVD];
__device__ float g_y2[ROWS*CVD];
__device__ float g_hdn[ROWS*FFN];
// pre-split weights, k-pair-packed bf16x2 hi/lo, layout [K/2][N]
__device__ uint32_t g_wqh[(CVD/2)*CVD], g_wql[(CVD/2)*CVD];
__device__ uint32_t g_woh[(CVD/2)*CVD], g_wol[(CVD/2)*CVD];
__device__ uint32_t g_w1h[(CVD/2)*FFN], g_w1l[(CVD/2)*FFN];
__device__ uint32_t g_w2h[(FFN/2)*CVD], g_w2l[(FFN/2)*CVD];

__device__ __forceinline__ void bf16_split_pack(float x0, float x1, uint32_t& hi, uint32_t& lo) {
    __nv_bfloat16 h0 = __float2bfloat16_rn(x0);
    __nv_bfloat16 h1 = __float2bfloat16_rn(x1);
    __nv_bfloat16 l0 = __float2bfloat16_rn(x0 - __bfloat162float(h0));
    __nv_bfloat16 l1 = __float2bfloat16_rn(x1 - __bfloat162float(h1));
    hi = (uint32_t)__bfloat16_as_ushort(h0) | ((uint32_t)__bfloat16_as_ushort(h1) << 16);
    lo = (uint32_t)__bfloat16_as_ushort(l0) | ((uint32_t)__bfloat16_as_ushort(l1) << 16);
}

// ---------------- weight split+pack: W[K][N] fp32 -> Wh/Wl[K/2][N] bf16x2 ----------------
__global__ __launch_bounds__(256) void wsplit_kernel(const float* __restrict__ W,
                                                     uint32_t* __restrict__ Wh,
                                                     uint32_t* __restrict__ Wl,
                                                     int N) {
    int idx = blockIdx.x * 256 + threadIdx.x;
    int k2 = idx / N, n = idx - k2 * N;
    float x0 = W[(size_t)(2*k2) * N + n];
    float x1 = W[(size_t)(2*k2 + 1) * N + n];
    uint32_t h, l;
    bf16_split_pack(x0, x1, h, l);
    Wh[idx] = h; Wl[idx] = l;
}

// ---------------- LN1 ----------------
__global__ __launch_bounds__(256) void ln1_kernel(const float* __restrict__ in,
                                                  const float* __restrict__ g,
                                                  const float* __restrict__ b) {
    int warp = (blockIdx.x * blockDim.x + threadIdx.x) >> 5;
    int lane = threadIdx.x & 31;
    const float* row = in + (size_t)warp * CVD;
    float v[8]; float s = 0.f, ss = 0.f;
#pragma unroll
    for (int i = 0; i < 8; i++) { v[i] = row[lane*8 + i]; s += v[i]; ss += v[i]*v[i]; }
#pragma unroll
    for (int o = 16; o; o >>= 1) { s += __shfl_xor_sync(~0u, s, o); ss += __shfl_xor_sync(~0u, ss, o); }
    float mu  = s * (1.f/CVD);
    float inv = rsqrtf(ss * (1.f/CVD) - mu*mu + 1e-5f);
    float* orow = g_x + (size_t)warp * CVD;
#pragma unroll
    for (int i = 0; i < 8; i++) { int c = lane*8 + i; orow[c] = (v[i]-mu)*inv*g[c] + b[c]; }
}

// ---------------- LN2 + residual ----------------
__global__ __launch_bounds__(256) void ln2res_kernel(const float* __restrict__ g,
                                                     const float* __restrict__ b,
                                                     const float* __restrict__ alpha_p) {
    int warp = (blockIdx.x * blockDim.x + threadIdx.x) >> 5;
    int lane = threadIdx.x & 31;
    float alpha = alpha_p[0];
    const float* xr = g_x    + (size_t)warp * CVD;
    const float* pr = g_proj + (size_t)warp * CVD;
    float v[8]; float s = 0.f, ss = 0.f;
#pragma unroll
    for (int i = 0; i < 8; i++) {
        int c = lane*8 + i;
        v[i] = xr[c] + alpha * pr[c];
        s += v[i]; ss += v[i]*v[i];
    }
#pragma unroll
    for (int o = 16; o; o >>= 1) { s += __shfl_xor_sync(~0u, s, o); ss += __shfl_xor_sync(~0u, ss, o); }
    float mu  = s * (1.f/CVD);
    float inv = rsqrtf(ss * (1.f/CVD) - mu*mu + 1e-5f);
    float* orow = g_y2 + (size_t)warp * CVD;
#pragma unroll
    for (int i = 0; i < 8; i++) { int c = lane*8 + i; orow[c] = (v[i]-mu)*inv*g[c] + b[c]; }
}

// ---------------- K/V projection (per-token, proven best) ----------------
__global__ __launch_bounds__(256) void kv_kernel(const float* __restrict__ text,
                                                 const float* __restrict__ Wk, const float* __restrict__ bk,
                                                 const float* __restrict__ Wv, const float* __restrict__ bv) {
    int bt = blockIdx.x;
    int b  = bt / NT, t = bt - b * NT;
    int c  = threadIdx.x;
    __shared__ float txt[CTD];
    __shared__ float red[256];
    const float* trow = text + (size_t)bt * CTD;
    txt[c] = trow[c]; txt[c+256] = trow[c+256];
    __syncthreads();
    red[c] = fabsf(txt[c]) + fabsf(txt[c+256]);
    __syncthreads();
    for (int s = 128; s; s >>= 1) { if (c < s) red[c] += red[c+s]; __syncthreads(); }
    if (c == 0) g_pad[bt] = (red[0] <= 1e-6f);
    float kc = bk[c], vc = bv[c];
#pragma unroll 4
    for (int kk = 0; kk < CTD; kk++) {
        float tv = txt[kk];
        kc += tv * Wk[kk*CVD + c];
        vc += tv * Wv[kk*CVD + c];
    }
    float ss = kc * kc;
#pragma unroll
    for (int o = 16; o; o >>= 1) ss += __shfl_xor_sync(~0u, ss, o);
    kc /= fmaxf(sqrtf(ss), 1e-6f);
    int h = c >> 5, d = c & 31;
    g_kT[((b*NHH + h)*DH + d)*TPAD + t] = kc;
    g_v[(size_t)bt*CVD + c] = vc;
}

// ---------------- order-preserving float<->uint ----------------
__device__ __forceinline__ uint32_t ford(float f) {
    uint32_t u = __float_as_uint(f);
    return (u & 0x80000000u) ? ~u : (u | 0x80000000u);
}
__device__ __forceinline__ float finv(uint32_t m) {
    uint32_t u = (m & 0x80000000u) ? (m ^ 0x80000000u) : ~m;
    return __uint_as_float(u);
}

// ---------------- attention: 2 rows per block, warp per head; redux top-5 ----------------
__global__ __launch_bounds__(256) void attn_kernel(const float* __restrict__ logit_scale) {
    int row0 = blockIdx.x * 2;
    int b    = row0 >> 12;
    int tid  = threadIdx.x;
    int h = tid >> 5, lane = tid & 31;
    __shared__ float qs[2][CVD];
    __shared__ int   spad[NT];
    qs[0][tid] = g_q[(size_t)row0 * CVD + tid];
    qs[1][tid] = g_q[(size_t)(row0 + 1) * CVD + tid];
    if (tid < NT) spad[tid] = g_pad[b*NT + tid];
    __syncthreads();

    float ls = logit_scale[0];
    float scale = expf(fminf(fmaxf(ls, -2.f), 2.f)) * 0.17677669529663687f;

    const float* kT = g_kT + ((size_t)(b*NHH + h) * DH) * TPAD;
    float acc[2][3] = {};
#pragma unroll
    for (int d = 0; d < DH; d++) {
        const float* kr = kT + d*TPAD;
        float k0 = kr[lane], k1 = kr[lane + 32], k2 = kr[lane + 64];
        float q0 = qs[0][h*DH + d];
        float q1 = qs[1][h*DH + d];
        acc[0][0] += q0 * k0; acc[0][1] += q0 * k1; acc[0][2] += q0 * k2;
        acc[1][0] += q1 * k0; acc[1][1] += q1 * k1; acc[1][2] += q1 * k2;
    }

    bool p0 = spad[lane];
    bool p1 = (lane + 32 >= NT) || spad[lane + 32];
    bool p2 = (lane + 64 >= NT) || spad[lane + 64];

#pragma unroll
    for (int rr = 0; rr < 2; rr++) {
        float s0 = !p0 ? acc[rr][0] * scale : -INFINITY;
        float s1 = !p1 ? acc[rr][1] * scale : -INFINITY;
        float s2 = !p2 ? acc[rr][2] * scale : -INFINITY;

        uint32_t o0 = ford(s0), o1 = ford(s1), o2 = ford(s2);

        float topv[TOPM]; int topt[TOPM];
#pragma unroll
        for (int it = 0; it < TOPM; it++) {
            uint32_t loc = o0 > o1 ? o0 : o1;
            if (o2 > loc) loc = o2;
            uint32_t m = __reduce_max_sync(0xffffffffu, loc);
            topv[it] = finv(m);
            int t;
            unsigned b0 = __ballot_sync(0xffffffffu, o0 == m);
            if (b0) t = __ffs(b0) - 1;
            else {
                unsigned b1 = __ballot_sync(0xffffffffu, o1 == m);
                if (b1) t = 32 + __ffs(b1) - 1;
                else {
                    unsigned b2 = __ballot_sync(0xffffffffu, o2 == m);
                    t = 64 + __ffs(b2) - 1;
                }
            }
            topt[it] = t;
            if ((t & 31) == lane) {
                if (t < 32) o0 = 0u; else if (t < 64) o1 = 0u; else o2 = 0u;
            }
        }

        float outv = 0.f;
        float mx = topv[0];
        if (!(mx == -INFINITY)) {
            float e[TOPM]; float ws = 0.f;
#pragma unroll
            for (int i = 0; i < TOPM; i++) { e[i] = expf(topv[i] - mx); ws += e[i]; }
            float inv = 1.f / ws;
            const float* vb = g_v + (size_t)b * NT * CVD + h * DH + lane;
#pragma unroll
            for (int i = 0; i < TOPM; i++) outv += (e[i] * inv) * vb[(size_t)topt[i] * CVD];
        }
        g_aligned[(size_t)(row0 + rr) * CVD + h*DH + lane] = outv;
    }
}

// ---------------- mma / ldmatrix helpers ----------------
__device__ __forceinline__ void mma16(float* c, const uint32_t* a, const uint32_t* b) {
    asm volatile("mma.sync.aligned.m16n8k16.row.col.f32.bf16.bf16.f32 "
        "{%0,%1,%2,%3}, {%4,%5,%6,%7}, {%8,%9}, {%0,%1,%2,%3};"
        : "+f"(c[0]), "+f"(c[1]), "+f"(c[2]), "+f"(c[3])
        : "r"(a[0]), "r"(a[1]), "r"(a[2]), "r"(a[3]), "r"(b[0]), "r"(b[1]));
}
__device__ __forceinline__ void ldsm4(uint32_t* r, uint32_t saddr) {
    asm volatile("ldmatrix.sync.aligned.m8n8.x4.shared.b16 {%0,%1,%2,%3}, [%4];"
        : "=r"(r[0]), "=r"(r[1]), "=r"(r[2]), "=r"(r[3]) : "r"(saddr));
}

// ---------------- split-bf16 GEMM: A split at staging (fp32 in), B pre-packed [K/2][N] ----------------
// A/B fragments via ldmatrix (R14 layouts). mode: 0 plain, 1 gelu, 2 l2norm, 3 +res.
#define ASTRIDE 12
#define BSTRIDE 12
__global__ __launch_bounds__(256) void gemm_bf16s_kernel(const float* __restrict__ A,
                                                         const uint32_t* __restrict__ Bhp,
                                                         const uint32_t* __restrict__ Blp,
                                                         const float* __restrict__ bias,
                                                         const float* __restrict__ res,
                                                         float* __restrict__ C,
                                                         int K, int N, int mode) {
    __shared__ uint32_t AhS[2][128*ASTRIDE], AlS[2][128*ASTRIDE];
    __shared__ uint32_t BhS[2][64*BSTRIDE], BlS[2][64*BSTRIDE];

    int tid  = threadIdx.x;
    int lane = tid & 31, wid = tid >> 5;
    int warpM = wid & 3, warpN = wid >> 2;
    int g = lane >> 2, t4 = lane & 3;
    int m0 = blockIdx.y * 128, n0 = blockIdx.x * 64;
    int mbase = warpM * 32, nbase = warpN * 32;

    float c[2][4][4];
#pragma unroll
    for (int i = 0; i < 2; i++)
#pragma unroll
        for (int j = 0; j < 4; j++)
#pragma unroll
            for (int l = 0; l < 4; l++) c[i][j][l] = 0.f;

    int ar   = tid >> 1;
    int ha   = tid & 1;
    int aoff = ar * ASTRIDE + ha * 4;
    int bn   = tid & 63;
    int k2b  = (tid >> 6) * 2;
    const float* Aptr = A + (size_t)(m0 + ar) * K + 8*ha;
    const uint32_t* Bph = Bhp + (size_t)k2b * N + n0 + bn;
    const uint32_t* Bpl = Blp + (size_t)k2b * N + n0 + bn;

    int lrow = lane & 15;
    int lkof = (lane >> 4) * 4;
    int bm   = lane >> 3;
    int brow = ((bm >> 1) << 3) + (lane & 7);
    int bkof = (bm & 1) * 4;

    float4 av0, av1;
    uint32_t bh0, bh1, bl0, bl1;
    av0 = *(const float4*)(Aptr);
    av1 = *(const float4*)(Aptr + 4);
    bh0 = Bph[0]; bh1 = Bph[N];
    bl0 = Bpl[0]; bl1 = Bpl[N];

    // stage tile 0
    {
        uint32_t h0,l0,h1,l1,h2,l2,h3,l3;
        bf16_split_pack(av0.x, av0.y, h0, l0);
        bf16_split_pack(av0.z, av0.w, h1, l1);
        bf16_split_pack(av1.x, av1.y, h2, l2);
        bf16_split_pack(av1.z, av1.w, h3, l3);
        *(uint4*)&AhS[0][aoff] = make_uint4(h0, h1, h2, h3);
        *(uint4*)&AlS[0][aoff] = make_uint4(l0, l1, l2, l3);
        *(uint2*)&BhS[0][bn*BSTRIDE + k2b] = make_uint2(bh0, bh1);
        *(uint2*)&BlS[0][bn*BSTRIDE + k2b] = make_uint2(bl0, bl1);
    }

    int stage = 0;
    for (int k0 = 0; k0 < K; k0 += 16) {
        __syncthreads();
        bool more = (k0 + 16) < K;
        if (more) {
            av0 = *(const float4*)(Aptr + k0 + 16);
            av1 = *(const float4*)(Aptr + k0 + 20);
            const uint32_t* bph = Bph + (size_t)((k0 >> 1) + 8) * N;
            const uint32_t* bpl = Bpl + (size_t)((k0 >> 1) + 8) * N;
            bh0 = bph[0]; bh1 = bph[N];
            bl0 = bpl[0]; bl1 = bpl[N];
        }

        uint32_t ah[2][4], al[2][4], bh[4][2], blo[4][2];
#pragma unroll
        for (int mt = 0; mt < 2; mt++) {
            int r = mbase + mt*16 + lrow;
            uint32_t addrH = (uint32_t)__cvta_generic_to_shared(&AhS[stage][r*ASTRIDE + lkof]);
            uint32_t addrL = (uint32_t)__cvta_generic_to_shared(&AlS[stage][r*ASTRIDE + lkof]);
            ldsm4(ah[mt], addrH);
            ldsm4(al[mt], addrL);
        }
#pragma unroll
        for (int pair = 0; pair < 2; pair++) {
            int nrow = nbase + pair*16 + brow;
            uint32_t addrH = (uint32_t)__cvta_generic_to_shared(&BhS[stage][nrow*BSTRIDE + bkof]);
            uint32_t addrL = (uint32_t)__cvta_generic_to_shared(&BlS[stage][nrow*BSTRIDE + bkof]);
            uint32_t tH[4], tL[4];
            ldsm4(tH, addrH);
            ldsm4(tL, addrL);
            bh[pair*2  ][0] = tH[0]; bh[pair*2  ][1] = tH[1];
            bh[pair*2+1][0] = tH[2]; bh[pair*2+1][1] = tH[3];
            blo[pair*2  ][0] = tL[0]; blo[pair*2  ][1] = tL[1];
            blo[pair*2+1][0] = tL[2]; blo[pair*2+1][1] = tL[3];
        }
#pragma unroll
        for (int mt = 0; mt < 2; mt++)
#pragma unroll
            for (int nt = 0; nt < 4; nt++) {
                mma16(c[mt][nt], al[mt], bh[nt]);
                mma16(c[mt][nt], ah[mt], blo[nt]);
                mma16(c[mt][nt], ah[mt], bh[nt]);
            }

        if (more) {
            int ns = stage ^ 1;
            uint32_t h0,l0,h1,l1,h2,l2,h3,l3;
            bf16_split_pack(av0.x, av0.y, h0, l0);
            bf16_split_pack(av0.z, av0.w, h1, l1);
            bf16_split_pack(av1.x, av1.y, h2, l2);
            bf16_split_pack(av1.z, av1.w, h3, l3);
            *(uint4*)&AhS[ns][aoff] = make_uint4(h0, h1, h2, h3);
            *(uint4*)&AlS[ns][aoff] = make_uint4(l0, l1, l2, l3);
            *(uint2*)&BhS[ns][bn*BSTRIDE + k2b] = make_uint2(bh0, bh1);
            *(uint2*)&BlS[ns][bn*BSTRIDE + k2b] = make_uint2(bl0, bl1);
        }
        stage ^= 1;
    }

    // epilogue
#pragma unroll
    for (int mt = 0; mt < 2; mt++)
#pragma unroll
        for (int nt = 0; nt < 4; nt++) {
            int col = n0 + nbase + nt*8 + t4*2;
            float b0v = bias[col], b1v = bias[col + 1];
            c[mt][nt][0] += b0v; c[mt][nt][1] += b1v;
            c[mt][nt][2] += b0v; c[mt][nt][3] += b1v;
        }

    if (mode == 2) {
#pragma unroll
        for (int mt = 0; mt < 2; mt++) {
            float ss0 = 0.f, ss1 = 0.f;
#pragma unroll
            for (int nt = 0; nt < 4; nt++) {
                ss0 += c[mt][nt][0]*c[mt][nt][0] + c[mt][nt][1]*c[mt][nt][1];
                ss1 += c[mt][nt][2]*c[mt][nt][2] + c[mt][nt][3]*c[mt][nt][3];
            }
            ss0 += __shfl_xor_sync(~0u, ss0, 1); ss0 += __shfl_xor_sync(~0u, ss0, 2);
            ss1 += __shfl_xor_sync(~0u, ss1, 1); ss1 += __shfl_xor_sync(~0u, ss1, 2);
            float i0 = 1.f / fmaxf(sqrtf(ss0), 1e-6f);
            float i1 = 1.f / fmaxf(sqrtf(ss1), 1e-6f);
#pragma unroll
            for (int nt = 0; nt < 4; nt++) {
                c[mt][nt][0] *= i0; c[mt][nt][1] *= i0;
                c[mt][nt][2] *= i1; c[mt][nt][3] *= i1;
            }
        }
    }

#pragma unroll
    for (int mt = 0; mt < 2; mt++)
#pragma unroll
        for (int nt = 0; nt < 4; nt++) {
            int col = n0 + nbase + nt*8 + t4*2;
            size_t r0 = (size_t)(m0 + mbase + mt*16 + g);
            size_t r1 = r0 + 8;
            float v0 = c[mt][nt][0], v1 = c[mt][nt][1];
            float v2 = c[mt][nt][2], v3 = c[mt][nt][3];
            if (mode == 1) {
                v0 = 0.5f*v0*(1.f + erff(v0*0.70710678118654752f));
                v1 = 0.5f*v1*(1.f + erff(v1*0.70710678118654752f));
                v2 = 0.5f*v2*(1.f + erff(v2*0.70710678118654752f));
                v3 = 0.5f*v3*(1.f + erff(v3*0.70710678118654752f));
            }
            if (mode == 3) {
                v0 += res[r0*N + col]; v1 += res[r0*N + col + 1];
                v2 += res[r1*N + col]; v3 += res[r1*N + col + 1];
            }
            *(float2*)&C[r0*N + col] = make_float2(v0, v1);
            *(float2*)&C[r1*N + col] = make_float2(v2, v3);
        }
}

// ---------------- launch ----------------
extern "C" void kernel_launch(void* const* d_in, const int* in_sizes, int n_in,
                              void* d_out, int out_size) {
    const float* vis   = (const float*)d_in[0];
    const float* text  = (const float*)d_in[1];
    const float* Wq    = (const float*)d_in[2];
    const float* bq    = (const float*)d_in[3];
    const float* Wk    = (const float*)d_in[4];
    const float* bk    = (const float*)d_in[5];
    const float* Wv    = (const float*)d_in[6];
    const float* bv    = (const float*)d_in[7];
    const float* Wo    = (const float*)d_in[8];
    const float* bo    = (const float*)d_in[9];
    const float* g1    = (const float*)d_in[10];
    const float* b1    = (const float*)d_in[11];
    const float* g2    = (const float*)d_in[12];
    const float* b2    = (const float*)d_in[13];
    const float* Wf1   = (const float*)d_in[14];
    const float* bf1   = (const float*)d_in[15];
    const float* Wf2   = (const float*)d_in[16];
    const float* bf2   = (const float*)d_in[17];
    const float* ls    = (const float*)d_in[18];
    const float* alpha = (const float*)d_in[19];
    float* out = (float*)d_out;

    float *px, *pq, *paligned, *pproj, *py2, *phdn;
    uint32_t *pwqh, *pwql, *pwoh, *pwol, *pw1h, *pw1l, *pw2h, *pw2l;
    cudaGetSymbolAddress((void**)&px,       g_x);
    cudaGetSymbolAddress((void**)&pq,       g_q);
    cudaGetSymbolAddress((void**)&paligned, g_aligned);
    cudaGetSymbolAddress((void**)&pproj,    g_proj);
    cudaGetSymbolAddress((void**)&py2,      g_y2);
    cudaGetSymbolAddress((void**)&phdn,     g_hdn);
    cudaGetSymbolAddress((void**)&pwqh, g_wqh); cudaGetSymbolAddress((void**)&pwql, g_wql);
    cudaGetSymbolAddress((void**)&pwoh, g_woh); cudaGetSymbolAddress((void**)&pwol, g_wol);
    cudaGetSymbolAddress((void**)&pw1h, g_w1h); cudaGetSymbolAddress((void**)&pw1l, g_w1l);
    cudaGetSymbolAddress((void**)&pw2h, g_w2h); cudaGetSymbolAddress((void**)&pw2l, g_w2l);

    // side stream: Wq split (early, for qGEMM) -> kv (for attn) -> remaining weight splits
    cudaStream_t s2;
    cudaEvent_t evA, evW, evB, evC;
    cudaStreamCreateWithFlags(&s2, cudaStreamNonBlocking);
    cudaEventCreateWithFlags(&evA, cudaEventDisableTiming);
    cudaEventCreateWithFlags(&evW, cudaEventDisableTiming);
    cudaEventCreateWithFlags(&evB, cudaEventDisableTiming);
    cudaEventCreateWithFlags(&evC, cudaEventDisableTiming);

    cudaEventRecord(evA, 0);
    cudaStreamWaitEvent(s2, evA, 0);
    wsplit_kernel<<<(CVD/2)*CVD/256, 256, 0, s2>>>(Wq, pwqh, pwql, CVD);
    cudaEventRecord(evW, s2);
    kv_kernel<<<NB*NT, 256, 0, s2>>>(text, Wk, bk, Wv, bv);
    cudaEventRecord(evB, s2);
    wsplit_kernel<<<(CVD/2)*CVD/256, 256, 0, s2>>>(Wo,  pwoh, pwol, CVD);
    wsplit_kernel<<<(CVD/2)*FFN/256, 256, 0, s2>>>(Wf1, pw1h, pw1l, FFN);
    wsplit_kernel<<<(FFN/2)*CVD/256, 256, 0, s2>>>(Wf2, pw2h, pw2l, CVD);
    cudaEventRecord(evC, s2);

    // main: ln1 (overlaps Wq split) -> qGEMM -> attn -> proj -> ln2 -> FFN1 -> FFN2
    ln1_kernel<<<ROWS/8, 256>>>(vis, g1, b1);
    cudaStreamWaitEvent(0, evW, 0);
    gemm_bf16s_kernel<<<dim3(CVD/64, ROWS/128), 256>>>(
        px, pwqh, pwql, bq, nullptr, pq, CVD, CVD, 2);
    cudaStreamWaitEvent(0, evB, 0);
    attn_kernel<<<ROWS/2, 256>>>(ls);
    cudaStreamWaitEvent(0, evC, 0);
    gemm_bf16s_kernel<<<dim3(CVD/64, ROWS/128), 256>>>(
        paligned, pwoh, pwol, bo, nullptr, pproj, CVD, CVD, 0);
    ln2res_kernel<<<ROWS/8, 256>>>(g2, b2, alpha);
    gemm_bf16s_kernel<<<dim3(FFN/64, ROWS/128), 256>>>(
        py2, pw1h, pw1l, bf1, nullptr, phdn, CVD, FFN, 1);
    gemm_bf16s_kernel<<<dim3(CVD/64, ROWS/128), 256>>>(
        phdn, pw2h, pw2l, bf2, py2, out, FFN, CVD, 3);
}